// round 13
// baseline (speedup 1.0000x reference)
#include <cuda_runtime.h>
#include <cuda_fp16.h>
#include <cstdint>

#define BATCH   2048
#define NTOK    64
#define DIM     256
#define HEADS   8
#define HEADDIM 32
#define MASK_NW 64

// fp16 staging: W (q|k|v), scratch Q/K/V; CMB fp32. (X converted in-GEMM.)
__device__ __half g_Wh[3 * DIM * DIM];
__device__ __half g_Q[(size_t)BATCH * NTOK * DIM];
__device__ __half g_K[(size_t)BATCH * NTOK * DIM];
__device__ __half g_V[(size_t)BATCH * NTOK * DIM];
__device__ float  g_CMB[(size_t)MASK_NW * HEADS * NTOK * NTOK];

__device__ __forceinline__ uint32_t h2bits(float a, float b) {
    __half2 h = __floats2half2_rn(a, b);
    return *(uint32_t*)&h;
}
__device__ __forceinline__ uint32_t smem_u32(const void* p) {
    return (uint32_t)__cvta_generic_to_shared(p);
}
__device__ __forceinline__ void ldsm_x4(uint32_t* r, uint32_t a) {
    asm volatile("ldmatrix.sync.aligned.m8n8.x4.shared.b16 {%0,%1,%2,%3}, [%4];"
        : "=r"(r[0]), "=r"(r[1]), "=r"(r[2]), "=r"(r[3]) : "r"(a));
}
__device__ __forceinline__ void ldsm_x4t(uint32_t* r, uint32_t a) {
    asm volatile("ldmatrix.sync.aligned.m8n8.x4.trans.shared.b16 {%0,%1,%2,%3}, [%4];"
        : "=r"(r[0]), "=r"(r[1]), "=r"(r[2]), "=r"(r[3]) : "r"(a));
}
__device__ __forceinline__ void mma16(float* d, const uint32_t* a, const uint32_t* b) {
    asm("mma.sync.aligned.m16n8k16.row.col.f32.f16.f16.f32 "
        "{%0,%1,%2,%3}, {%4,%5,%6,%7}, {%8,%9}, {%0,%1,%2,%3};"
        : "+f"(d[0]), "+f"(d[1]), "+f"(d[2]), "+f"(d[3])
        : "r"(a[0]), "r"(a[1]), "r"(a[2]), "r"(a[3]), "r"(b[0]), "r"(b[1]));
}
__device__ __forceinline__ void cp16(uint32_t dst, const void* src) {
    asm volatile("cp.async.cg.shared.global [%0], [%1], 16;" :: "r"(dst), "l"(src));
}
__device__ __forceinline__ void cp_commit() {
    asm volatile("cp.async.commit_group;");
}
template <int N>
__device__ __forceinline__ void cp_wait() {
    asm volatile("cp.async.wait_group %0;" :: "n"(N));
}

// ---------------------------------------------------------------------------
// Kernel 0: prep W (fp16) + combined mask/rel-bias. Blocks [0,96): W;
// [96, 8288): CMB.
// ---------------------------------------------------------------------------
__global__ void prep_wc(const float* __restrict__ Wq,
                        const float* __restrict__ Wk,
                        const float* __restrict__ Wv,
                        const float* __restrict__ mask,
                        const float* __restrict__ bt,
                        const int*   __restrict__ ri)
{
    const int bid = blockIdx.x;
    if (bid < 96) {
        const int i8 = (bid * 256 + threadIdx.x) * 8;
        const int t3 = i8 >> 16;
        const int off = i8 & 65535;
        const float* src = (t3 == 0) ? Wq : (t3 == 1) ? Wk : Wv;
        const float4 a = *(const float4*)(src + off);
        const float4 b = *(const float4*)(src + off + 4);
        uint32_t r[4] = { h2bits(a.x, a.y), h2bits(a.z, a.w),
                          h2bits(b.x, b.y), h2bits(b.z, b.w) };
        *(uint4*)(g_Wh + i8) = *(uint4*)r;
    } else {
        const int idx = (bid - 96) * 256 + threadIdx.x;
        const int p = idx & 4095;
        const int h = (idx >> 12) & 7;
        const int w = idx >> 15;
        g_CMB[idx] = mask[w * 4096 + p] + bt[ri[p] * 8 + h];
    }
}

// ---------------------------------------------------------------------------
// Kernel 1: X-resident QKV GEMM. One CTA per 128-row m-block (1024 CTAs).
//   X loaded ONCE per CTA directly from fp32 (LDG -> cvt -> swizzled STS).
//   6 output slabs x BK=64 weight tiles stream through a 3-stage swizzled
//   cp.async pipeline; ONE __syncthreads per 64-k iteration (24 total).
//   8 warps, warp tile 32x64, 2 CTA/SM.
//   Swizzle (both X and B): byte_col ^ ((row & 7) << 4)
//   X rows 512 B; B rows 128 B.
// ---------------------------------------------------------------------------
#define GEMM_SMEM (128 * 256 * 2 + 3 * 128 * 64 * 2)   // 65536 + 49152 = 114688 B

__global__ __launch_bounds__(256, 2) void qkv_gemm_tc(
    const float* __restrict__ X,
    const float* __restrict__ Bq, const float* __restrict__ Bk,
    const float* __restrict__ Bv)
{
    extern __shared__ __half sm[];
    __half* Xs  = sm;                 // 128 x 256, swizzled, 512 B rows
    __half* Bsm = sm + 128 * 256;     // 3 stages x 128 x 64, swizzled, 128 B rows

    const int tid  = threadIdx.x;
    const int m0   = blockIdx.x * 128;
    const int lane = tid & 31;
    const int warp = tid >> 5;
    const int g  = lane >> 2;
    const int tg = lane & 3;
    const int wm = (warp >> 1) * 32;
    const int wn = (warp & 1) * 64;

    const uint32_t XsB = smem_u32(Xs);
    const uint32_t BsB = smem_u32(Bsm);
    constexpr uint32_t BSTG = 128 * 64 * 2;   // 16384 B stage stride

    // ---- B stage load: thread = (row, 64B chunk) -> 4 x cp16 ----
    const int br = tid >> 1;                  // row 0..127
    const int bq4 = (tid & 1) * 64;           // byte offset within row: 0 or 64
    const int bsw = (br & 7) << 4;

    auto bsrc = [&](int it) -> const __half* {
        const int nsel = it >> 2, kt = it & 3;
        const int t3 = nsel >> 1, nl0 = (nsel & 1) << 7;
        return g_Wh + t3 * 65536 + (size_t)(nl0 + br) * 256 + kt * 64 + bq4 / 2;
    };
    auto bpush = [&](int it, uint32_t stage_base) {
        const __half* s = bsrc(it);
        #pragma unroll
        for (int j = 0; j < 4; j++)
            cp16(stage_base + br * 128 + ((bq4 + j * 16) ^ bsw), s + j * 8);
    };

    // prologue: B stages 0,1 -> commit groups 0,1 (before X so they overlap)
    bpush(0, BsB);           cp_commit();
    bpush(1, BsB + BSTG);    cp_commit();

    // ---- one-time X tile load: fp32 LDG -> fp16 -> swizzled STS ----
    {
        const int ar = tid >> 1;            // row 0..127
        const int ah = tid & 1;             // 128-float half of the row
        const float* xsrc = X + (size_t)(m0 + ar) * DIM + ah * 128;
        char* xrow = (char*)Xs + ar * 512;
        const int sw = (ar & 7) << 4;
        #pragma unroll
        for (int i = 0; i < 16; i++) {
            const float4 a = *(const float4*)(xsrc + i * 8);
            const float4 b = *(const float4*)(xsrc + i * 8 + 4);
            uint4 v = { h2bits(a.x, a.y), h2bits(a.z, a.w),
                        h2bits(b.x, b.y), h2bits(b.z, b.w) };
            *(uint4*)(xrow + ((ah * 256 + i * 16) ^ sw)) = v;
        }
    }

    // ---- ldmatrix lane addresses ----
    const int ra = (lane & 7) + ((lane >> 3) & 1) * 8;
    const int cab = (lane >> 4) * 16;       // bytes (0 or 16)
    uint32_t aArow[2]; int aAsw[2];
    #pragma unroll
    for (int mt = 0; mt < 2; mt++) {
        const int rr = wm + mt * 16 + ra;
        aArow[mt] = XsB + rr * 512;
        aAsw[mt]  = (rr & 7) << 4;
    }
    const int nbr = wn + (lane & 7) + (lane >> 4) * 8;   // B row (j=0)
    const int kb2 = ((lane >> 3) & 1) * 16;              // B byte col base
    const uint32_t aBrow = BsB + nbr * 128;
    const int bswl = (nbr & 7) << 4;                     // same for all j (j*16 ≡ 0 mod 8)

    float acc[2][8][4] = {};

    for (int nsel = 0; nsel < 6; nsel++) {
        #pragma unroll
        for (int kt = 0; kt < 4; kt++) {
            const int it = nsel * 4 + kt;
            // stage it = group it; committed = it+2 -> pending 1
            cp_wait<1>();
            __syncthreads();

            if (it + 2 < 24)
                bpush(it + 2, BsB + ((it + 2) % 3) * BSTG);
            cp_commit();   // uniform group accounting

            const uint32_t s = (it % 3) * BSTG;
            #pragma unroll
            for (int kcb = 0; kcb < 4; kcb++) {
                const int akb = (kt * 64 + kcb * 16) * 2 + cab;   // X byte col
                const int bkb = kcb * 32 + kb2;                   // B byte col
                uint32_t afr[2][4];
                ldsm_x4(afr[0], aArow[0] + (akb ^ aAsw[0]));
                ldsm_x4(afr[1], aArow[1] + (akb ^ aAsw[1]));
                uint32_t bfr[4][4];
                #pragma unroll
                for (int j = 0; j < 4; j++)
                    ldsm_x4(bfr[j], s + aBrow + j * 16 * 128 + (bkb ^ bswl));
                #pragma unroll
                for (int mt = 0; mt < 2; mt++)
                    #pragma unroll
                    for (int nt = 0; nt < 8; nt++)
                        mma16(acc[mt][nt], afr[mt], &bfr[nt >> 1][(nt & 1) * 2]);
            }
        }

        // ---- slab epilogue: bias add + store, reset acc ----
        {
            const int t3  = nsel >> 1;
            const int nl0 = (nsel & 1) << 7;
            const float* bias = (t3 == 0) ? Bq : (t3 == 1) ? Bk : Bv;
            __half* outp      = (t3 == 0) ? g_Q : (t3 == 1) ? g_K : g_V;
            #pragma unroll
            for (int nt = 0; nt < 8; nt++) {
                const int c = nl0 + wn + nt * 8 + tg * 2;
                const float b0 = bias[c], b1 = bias[c + 1];
                #pragma unroll
                for (int mt = 0; mt < 2; mt++) {
                    const int r = m0 + wm + mt * 16 + g;
                    *(uint32_t*)(outp + (size_t)r * DIM + c) =
                        h2bits(acc[mt][nt][0] + b0, acc[mt][nt][1] + b1);
                    *(uint32_t*)(outp + (size_t)(r + 8) * DIM + c) =
                        h2bits(acc[mt][nt][2] + b0, acc[mt][nt][3] + b1);
                    acc[mt][nt][0] = 0.f; acc[mt][nt][1] = 0.f;
                    acc[mt][nt][2] = 0.f; acc[mt][nt][3] = 0.f;
                }
            }
        }
    }
}

// ---------------------------------------------------------------------------
// Kernel 2: fp16 attention with ldmatrix. CTA = (window, head), 4 warps.
// ---------------------------------------------------------------------------
__global__ __launch_bounds__(128) void attn_tc(float* __restrict__ out)
{
    __shared__ __half qs[64 * 40];
    __shared__ __half ks[64 * 40];
    __shared__ __half vs[64 * 40];

    const int b = blockIdx.x;
    const int h = blockIdx.y;
    const int tid  = threadIdx.x;
    const int lane = tid & 31;
    const int warp = tid >> 5;
    const int g  = lane >> 2;
    const int tg = lane & 3;

    const size_t gbase = (size_t)b * (NTOK * DIM) + (size_t)h * HEADDIM;
    {
        const int r  = tid >> 1;
        const int ch = (tid & 1) * 16;
        const size_t go = gbase + (size_t)r * DIM + ch;
        *(uint4*)&qs[r * 40 + ch]     = *(const uint4*)(g_Q + go);
        *(uint4*)&qs[r * 40 + ch + 8] = *(const uint4*)(g_Q + go + 8);
        *(uint4*)&ks[r * 40 + ch]     = *(const uint4*)(g_K + go);
        *(uint4*)&ks[r * 40 + ch + 8] = *(const uint4*)(g_K + go + 8);
        *(uint4*)&vs[r * 40 + ch]     = *(const uint4*)(g_V + go);
        *(uint4*)&vs[r * 40 + ch + 8] = *(const uint4*)(g_V + go + 8);
    }
    __syncthreads();

    const int ra = (lane & 7) + ((lane >> 3) & 1) * 8;
    const int ca = (lane >> 4) * 8;
    const uint32_t aQ = smem_u32(&qs[(warp * 16 + ra) * 40 + ca]);
    const int nb = (lane & 7) + (lane >> 4) * 8;
    const int kb = ((lane >> 3) & 1) * 8;
    const uint32_t aK = smem_u32(&ks[nb * 40 + kb]);
    const uint32_t aV = smem_u32(&vs[ra * 40 + ca]);

    // ---- scores ----
    float sacc[8][4] = {};
    #pragma unroll
    for (int kc = 0; kc < HEADDIM; kc += 16) {
        uint32_t afr[4];
        ldsm_x4(afr, aQ + kc * 2);
        #pragma unroll
        for (int j = 0; j < 4; j++) {
            uint32_t bfr[4];
            ldsm_x4(bfr, aK + j * 16 * 80 + kc * 2);
            mma16(sacc[j * 2],     afr, &bfr[0]);
            mma16(sacc[j * 2 + 1], afr, &bfr[2]);
        }
    }

    // ---- scale + mask/bias ----
    const float scale = 0.17677669529663687f;
    const float* cmb = g_CMB + (((size_t)(b & (MASK_NW - 1)) * HEADS + h) << 12);
    const int r0 = warp * 16 + g;

    float v0[16], v1[16];
    #pragma unroll
    for (int nt = 0; nt < 8; nt++) {
        const int c0 = nt * 8 + tg * 2;
        const float2 m0v = *(const float2*)(cmb + r0 * 64 + c0);
        const float2 m1v = *(const float2*)(cmb + (r0 + 8) * 64 + c0);
        v0[nt * 2]     = sacc[nt][0] * scale + m0v.x;
        v0[nt * 2 + 1] = sacc[nt][1] * scale + m0v.y;
        v1[nt * 2]     = sacc[nt][2] * scale + m1v.x;
        v1[nt * 2 + 1] = sacc[nt][3] * scale + m1v.y;
    }

    // ---- register softmax ----
    {
        float mx0 = v0[0], mx1 = v1[0];
        #pragma unroll
        for (int i = 1; i < 16; i++) { mx0 = fmaxf(mx0, v0[i]); mx1 = fmaxf(mx1, v1[i]); }
        mx0 = fmaxf(mx0, __shfl_xor_sync(0xffffffffu, mx0, 1));
        mx0 = fmaxf(mx0, __shfl_xor_sync(0xffffffffu, mx0, 2));
        mx1 = fmaxf(mx1, __shfl_xor_sync(0xffffffffu, mx1, 1));
        mx1 = fmaxf(mx1, __shfl_xor_sync(0xffffffffu, mx1, 2));

        float s0 = 0.f, s1 = 0.f;
        #pragma unroll
        for (int i = 0; i < 16; i++) {
            v0[i] = __expf(v0[i] - mx0); s0 += v0[i];
            v1[i] = __expf(v1[i] - mx1); s1 += v1[i];
        }
        s0 += __shfl_xor_sync(0xffffffffu, s0, 1);
        s0 += __shfl_xor_sync(0xffffffffu, s0, 2);
        s1 += __shfl_xor_sync(0xffffffffu, s1, 1);
        s1 += __shfl_xor_sync(0xffffffffu, s1, 2);
        const float inv0 = 1.0f / s0, inv1 = 1.0f / s1;
        #pragma unroll
        for (int i = 0; i < 16; i++) { v0[i] *= inv0; v1[i] *= inv1; }
    }

    // ---- PV ----
    float oacc[4][4] = {};
    #pragma unroll
    for (int kt = 0; kt < 4; kt++) {
        uint32_t afr[4];
        afr[0] = h2bits(v0[4 * kt],     v0[4 * kt + 1]);
        afr[1] = h2bits(v1[4 * kt],     v1[4 * kt + 1]);
        afr[2] = h2bits(v0[4 * kt + 2], v0[4 * kt + 3]);
        afr[3] = h2bits(v1[4 * kt + 2], v1[4 * kt + 3]);
        #pragma unroll
        for (int p = 0; p < 2; p++) {
            uint32_t bfr[4];
            ldsm_x4t(bfr, aV + kt * 16 * 80 + p * 32);
            mma16(oacc[p * 2],     afr, &bfr[0]);
            mma16(oacc[p * 2 + 1], afr, &bfr[2]);
        }
    }

    // ---- output ----
    {
        float* ob = out + gbase;
        #pragma unroll
        for (int nt = 0; nt < 4; nt++) {
            const int c0 = nt * 8 + tg * 2;
            *(float2*)(ob + (size_t)r0 * DIM + c0)       = make_float2(oacc[nt][0], oacc[nt][1]);
            *(float2*)(ob + (size_t)(r0 + 8) * DIM + c0) = make_float2(oacc[nt][2], oacc[nt][3]);
        }
    }
}

// ---------------------------------------------------------------------------
extern "C" void kernel_launch(void* const* d_in, const int* in_sizes, int n_in,
                              void* d_out, int out_size)
{
    const float* hs   = (const float*)d_in[0];
    const float* mask = (const float*)d_in[1];
    const float* wq   = (const float*)d_in[2];
    const float* bq   = (const float*)d_in[3];
    const float* wk   = (const float*)d_in[4];
    const float* bk   = (const float*)d_in[5];
    const float* wv   = (const float*)d_in[6];
    const float* bv   = (const float*)d_in[7];
    const float* bt   = (const float*)d_in[8];
    const int*   ri   = (const int*)d_in[9];
    float* out = (float*)d_out;

    static bool attr_set = false;
    if (!attr_set) {
        cudaFuncSetAttribute(qkv_gemm_tc,
                             cudaFuncAttributeMaxDynamicSharedMemorySize, GEMM_SMEM);
        attr_set = true;
    }

    prep_wc<<<96 + 8192, 256>>>(wq, wk, wv, mask, bt, ri);

    qkv_gemm_tc<<<(BATCH * NTOK) / 128, 256, GEMM_SMEM>>>(hs, bq, bk, bv);

    dim3 attn_grid(BATCH, HEADS);
    attn_tc<<<attn_grid, 128>>>(out);
}

// round 14
// speedup vs baseline: 1.1252x; 1.1252x over previous
#include <cuda_runtime.h>
#include <cuda_fp16.h>
#include <cstdint>

#define BATCH   2048
#define NTOK    64
#define DIM     256
#define HEADS   8
#define HEADDIM 32
#define MASK_NW 64

// fp16 staging: X, W (q|k|v), scratch Q/K/V; CMB fp32
__device__ __half g_Xh[(size_t)BATCH * NTOK * DIM];
__device__ __half g_Wh[3 * DIM * DIM];
__device__ __half g_Q[(size_t)BATCH * NTOK * DIM];
__device__ __half g_K[(size_t)BATCH * NTOK * DIM];
__device__ __half g_V[(size_t)BATCH * NTOK * DIM];
__device__ float  g_CMB[(size_t)MASK_NW * HEADS * NTOK * NTOK];

__device__ __forceinline__ uint32_t h2bits(float a, float b) {
    __half2 h = __floats2half2_rn(a, b);
    return *(uint32_t*)&h;
}
__device__ __forceinline__ uint32_t smem_u32(const void* p) {
    return (uint32_t)__cvta_generic_to_shared(p);
}
__device__ __forceinline__ void ldsm_x4(uint32_t* r, uint32_t a) {
    asm volatile("ldmatrix.sync.aligned.m8n8.x4.shared.b16 {%0,%1,%2,%3}, [%4];"
        : "=r"(r[0]), "=r"(r[1]), "=r"(r[2]), "=r"(r[3]) : "r"(a));
}
__device__ __forceinline__ void ldsm_x4t(uint32_t* r, uint32_t a) {
    asm volatile("ldmatrix.sync.aligned.m8n8.x4.trans.shared.b16 {%0,%1,%2,%3}, [%4];"
        : "=r"(r[0]), "=r"(r[1]), "=r"(r[2]), "=r"(r[3]) : "r"(a));
}
__device__ __forceinline__ void mma16(float* d, const uint32_t* a, const uint32_t* b) {
    asm("mma.sync.aligned.m16n8k16.row.col.f32.f16.f16.f32 "
        "{%0,%1,%2,%3}, {%4,%5,%6,%7}, {%8,%9}, {%0,%1,%2,%3};"
        : "+f"(d[0]), "+f"(d[1]), "+f"(d[2]), "+f"(d[3])
        : "r"(a[0]), "r"(a[1]), "r"(a[2]), "r"(a[3]), "r"(b[0]), "r"(b[1]));
}
__device__ __forceinline__ void cp16(uint32_t dst, const void* src) {
    asm volatile("cp.async.cg.shared.global [%0], [%1], 16;" :: "r"(dst), "l"(src));
}
__device__ __forceinline__ void cp_commit() {
    asm volatile("cp.async.commit_group;");
}
template <int N>
__device__ __forceinline__ void cp_wait() {
    asm volatile("cp.async.wait_group %0;" :: "n"(N));
}

// ---------------------------------------------------------------------------
// Kernel 0: one-shot prep. Blocks [0,16384): X fp32->fp16; [16384,16480): W;
// [16480,24672): combined mask + rel-bias.
// ---------------------------------------------------------------------------
__global__ void prep_all(const float* __restrict__ X,
                         const float* __restrict__ Wq,
                         const float* __restrict__ Wk,
                         const float* __restrict__ Wv,
                         const float* __restrict__ mask,
                         const float* __restrict__ bt,
                         const int*   __restrict__ ri)
{
    const int bid = blockIdx.x;
    if (bid < 16384) {
        const size_t i8 = ((size_t)bid * 256 + threadIdx.x) * 8;
        const float4 a = *(const float4*)(X + i8);
        const float4 b = *(const float4*)(X + i8 + 4);
        uint32_t r[4] = { h2bits(a.x, a.y), h2bits(a.z, a.w),
                          h2bits(b.x, b.y), h2bits(b.z, b.w) };
        *(uint4*)(g_Xh + i8) = *(uint4*)r;
    } else if (bid < 16384 + 96) {
        const int i8 = ((bid - 16384) * 256 + threadIdx.x) * 8;
        const int t3 = i8 >> 16;
        const int off = i8 & 65535;
        const float* src = (t3 == 0) ? Wq : (t3 == 1) ? Wk : Wv;
        const float4 a = *(const float4*)(src + off);
        const float4 b = *(const float4*)(src + off + 4);
        uint32_t r[4] = { h2bits(a.x, a.y), h2bits(a.z, a.w),
                          h2bits(b.x, b.y), h2bits(b.z, b.w) };
        *(uint4*)(g_Wh + i8) = *(uint4*)r;
    } else {
        const int idx = (bid - 16480) * 256 + threadIdx.x;
        const int p = idx & 4095;
        const int h = (idx >> 12) & 7;
        const int w = idx >> 15;
        g_CMB[idx] = mask[w * 4096 + p] + bt[ri[p] * 8 + h];
    }
}

// ---------------------------------------------------------------------------
// Kernel 1: X-resident QKV GEMM (R11 verified). One CTA per 128-row m-block.
//   4-stage cp.async weight pipeline across 6 slabs; 8 warps; 2 CTA/SM.
// ---------------------------------------------------------------------------
#define GEMM_SMEM (128 * 256 * 2 + 4 * 128 * 40 * 2)   // 106496 B

__global__ __launch_bounds__(256, 2) void qkv_gemm_tc(
    const float* __restrict__ Bq, const float* __restrict__ Bk,
    const float* __restrict__ Bv)
{
    extern __shared__ __half sm[];
    __half* Xs  = sm;                 // 128 x 256, swizzled, 512 B rows
    __half* Bsm = sm + 128 * 256;     // 4 stages x 128 x 40

    const int tid  = threadIdx.x;
    const int m0   = blockIdx.x * 128;
    const int lane = tid & 31;
    const int warp = tid >> 5;
    const int g  = lane >> 2;
    const int tg = lane & 3;
    const int wm = (warp >> 1) * 32;
    const int wn = (warp & 1) * 64;

    const uint32_t XsB = smem_u32(Xs);
    const uint32_t BsB = smem_u32(Bsm);
    constexpr uint32_t BSTG = 128 * 40 * 2;

    // ---- one-time X tile load (swizzled) -> commit group 0 ----
    {
        const int ar = tid >> 1;
        const int ah = tid & 1;
        const __half* xsrc = g_Xh + (size_t)(m0 + ar) * DIM + ah * 128;
        const uint32_t rbase = XsB + ar * 512;
        const int sw = (ar & 7) << 4;
        #pragma unroll
        for (int i = 0; i < 16; i++) {
            const int col = ah * 256 + i * 16;
            cp16(rbase + (col ^ sw), xsrc + i * 8);
        }
        cp_commit();
    }

    // ---- B stage load ----
    const int br = tid >> 1;
    const int bh = (tid & 1) * 16;
    const uint32_t bdst = BsB + (br * 40 + bh) * 2;

    auto bsrc = [&](int it) -> const __half* {
        const int nsel = it >> 3, kt = it & 7;
        const int t3 = nsel >> 1, nl0 = (nsel & 1) << 7;
        return g_Wh + t3 * 65536 + (size_t)(nl0 + br) * 256 + kt * 32 + bh;
    };

    #pragma unroll
    for (int p = 0; p < 3; p++) {
        const __half* sp = bsrc(p);
        cp16(bdst + p * BSTG,      sp);
        cp16(bdst + p * BSTG + 16, sp + 8);
        cp_commit();
    }

    // ---- ldmatrix lane addresses ----
    const int ra = (lane & 7) + ((lane >> 3) & 1) * 8;
    const int cab = (lane >> 4) * 16;
    uint32_t aArow[2]; int aAsw[2];
    #pragma unroll
    for (int mt = 0; mt < 2; mt++) {
        const int rr = wm + mt * 16 + ra;
        aArow[mt] = XsB + rr * 512;
        aAsw[mt]  = (rr & 7) << 4;
    }
    const int nb = (lane & 7) + (lane >> 4) * 8;
    const int kb = ((lane >> 3) & 1) * 8;
    const uint32_t aB = BsB + ((wn + nb) * 40 + kb) * 2;

    float acc[2][8][4] = {};

    for (int nsel = 0; nsel < 6; nsel++) {
        #pragma unroll
        for (int kt = 0; kt < 8; kt++) {
            const int it = nsel * 8 + kt;
            cp_wait<2>();
            __syncthreads();

            if (it + 3 < 48) {
                const uint32_t sn = ((it + 3) & 3) * BSTG;
                const __half* s3 = bsrc(it + 3);
                cp16(bdst + sn,      s3);
                cp16(bdst + sn + 16, s3 + 8);
            }
            cp_commit();

            const uint32_t s = (it & 3) * BSTG;
            uint32_t afr[2][2][4];
            uint32_t bfr[2][4][4];
            #pragma unroll
            for (int kcb = 0; kcb < 2; kcb++) {
                const int akb = (kt * 32 + kcb * 16) * 2 + cab;
                ldsm_x4(afr[kcb][0], aArow[0] + (akb ^ aAsw[0]));
                ldsm_x4(afr[kcb][1], aArow[1] + (akb ^ aAsw[1]));
                #pragma unroll
                for (int j = 0; j < 4; j++)
                    ldsm_x4(bfr[kcb][j], aB + s + j * 1280 + kcb * 32);
            }
            #pragma unroll
            for (int kcb = 0; kcb < 2; kcb++)
                #pragma unroll
                for (int mt = 0; mt < 2; mt++)
                    #pragma unroll
                    for (int nt = 0; nt < 8; nt++)
                        mma16(acc[mt][nt], afr[kcb][mt],
                              &bfr[kcb][nt >> 1][(nt & 1) * 2]);
        }

        // ---- slab epilogue ----
        {
            const int t3  = nsel >> 1;
            const int nl0 = (nsel & 1) << 7;
            const float* bias = (t3 == 0) ? Bq : (t3 == 1) ? Bk : Bv;
            __half* outp      = (t3 == 0) ? g_Q : (t3 == 1) ? g_K : g_V;
            #pragma unroll
            for (int nt = 0; nt < 8; nt++) {
                const int c = nl0 + wn + nt * 8 + tg * 2;
                const float b0 = bias[c], b1 = bias[c + 1];
                #pragma unroll
                for (int mt = 0; mt < 2; mt++) {
                    const int r = m0 + wm + mt * 16 + g;
                    *(uint32_t*)(outp + (size_t)r * DIM + c) =
                        h2bits(acc[mt][nt][0] + b0, acc[mt][nt][1] + b1);
                    *(uint32_t*)(outp + (size_t)(r + 8) * DIM + c) =
                        h2bits(acc[mt][nt][2] + b0, acc[mt][nt][3] + b1);
                    acc[mt][nt][0] = 0.f; acc[mt][nt][1] = 0.f;
                    acc[mt][nt][2] = 0.f; acc[mt][nt][3] = 0.f;
                }
            }
        }
    }
}

// ---------------------------------------------------------------------------
// Kernel 2: window-batched fp16 attention. CTA = (window w, head h, group of
// 8 batches sharing the same mask slice). CMB loaded to smem ONCE; QKV
// double-buffered via cp.async across the 8-window loop. 4 warps.
// ---------------------------------------------------------------------------
__global__ __launch_bounds__(128) void attn_tc(float* __restrict__ out)
{
    __shared__ float  cmbs[4096];              // 16 KB
    __shared__ __half qkv[2][3][64 * 40];      // 2 bufs x (q,k,v) = 30720 B

    const int w   = blockIdx.x;    // mask window 0..63
    const int h   = blockIdx.y;    // head 0..7
    const int grp = blockIdx.z;    // 0..3 (8 windows each)
    const int tid  = threadIdx.x;
    const int lane = tid & 31;
    const int warp = tid >> 5;
    const int g  = lane >> 2;
    const int tg = lane & 3;

    // ---- CMB -> smem (once) ----
    {
        const float* cmb_g = g_CMB + (((size_t)w * HEADS + h) << 12);
        #pragma unroll
        for (int i = 0; i < 8; i++)
            ((float4*)cmbs)[tid + i * 128] = ((const float4*)cmb_g)[tid + i * 128];
    }

    // ---- QKV load mapping: thread = (token row, 16-half chunk) ----
    const int r  = tid >> 1;
    const int ch = (tid & 1) * 16;
    const uint32_t qkvB = smem_u32(&qkv[0][0][0]);
    constexpr uint32_t TBUF = 3 * 64 * 40 * 2;   // bytes per buffer
    constexpr uint32_t TTEN = 64 * 40 * 2;       // bytes per tensor
    const uint32_t ldst = (r * 40 + ch) * 2;

    auto qkv_load = [&](int i, int buf) {
        const int b = w + 64 * (grp * 8 + i);
        const size_t go = ((size_t)b * NTOK + r) * DIM + h * HEADDIM + ch;
        const uint32_t d = qkvB + buf * TBUF + ldst;
        cp16(d,                g_Q + go);
        cp16(d + 16,           g_Q + go + 8);
        cp16(d + TTEN,         g_K + go);
        cp16(d + TTEN + 16,    g_K + go + 8);
        cp16(d + 2 * TTEN,     g_V + go);
        cp16(d + 2 * TTEN + 16, g_V + go + 8);
    };

    // prologue: window 0 -> buf 0
    qkv_load(0, 0);
    cp_commit();

    // ---- ldmatrix lane address offsets (within a buffer) ----
    const int ra = (lane & 7) + ((lane >> 3) & 1) * 8;
    const int ca = (lane >> 4) * 8;
    const uint32_t oQ = ((warp * 16 + ra) * 40 + ca) * 2;
    const int nb = (lane & 7) + (lane >> 4) * 8;
    const int kb = ((lane >> 3) & 1) * 8;
    const uint32_t oK = TTEN + (nb * 40 + kb) * 2;
    const uint32_t oV = 2 * TTEN + (ra * 40 + ca) * 2;

    const float scale = 0.17677669529663687f;
    const int r0 = warp * 16 + g;

    for (int i = 0; i < 8; i++) {
        cp_wait<0>();
        __syncthreads();   // window i ready; prior compute on other buf done

        if (i < 7) qkv_load(i + 1, (i + 1) & 1);
        cp_commit();

        const uint32_t base = qkvB + (i & 1) * TBUF;
        const uint32_t aQ = base + oQ;
        const uint32_t aK = base + oK;
        const uint32_t aV = base + oV;

        // ---- scores ----
        float sacc[8][4] = {};
        #pragma unroll
        for (int kc = 0; kc < HEADDIM; kc += 16) {
            uint32_t afr[4];
            ldsm_x4(afr, aQ + kc * 2);
            #pragma unroll
            for (int j = 0; j < 4; j++) {
                uint32_t bfr[4];
                ldsm_x4(bfr, aK + j * 16 * 80 + kc * 2);
                mma16(sacc[j * 2],     afr, &bfr[0]);
                mma16(sacc[j * 2 + 1], afr, &bfr[2]);
            }
        }

        // ---- scale + mask/bias (from smem) ----
        float v0[16], v1[16];
        #pragma unroll
        for (int nt = 0; nt < 8; nt++) {
            const int c0 = nt * 8 + tg * 2;
            const float2 m0v = *(const float2*)&cmbs[r0 * 64 + c0];
            const float2 m1v = *(const float2*)&cmbs[(r0 + 8) * 64 + c0];
            v0[nt * 2]     = sacc[nt][0] * scale + m0v.x;
            v0[nt * 2 + 1] = sacc[nt][1] * scale + m0v.y;
            v1[nt * 2]     = sacc[nt][2] * scale + m1v.x;
            v1[nt * 2 + 1] = sacc[nt][3] * scale + m1v.y;
        }

        // ---- register softmax ----
        {
            float mx0 = v0[0], mx1 = v1[0];
            #pragma unroll
            for (int j = 1; j < 16; j++) { mx0 = fmaxf(mx0, v0[j]); mx1 = fmaxf(mx1, v1[j]); }
            mx0 = fmaxf(mx0, __shfl_xor_sync(0xffffffffu, mx0, 1));
            mx0 = fmaxf(mx0, __shfl_xor_sync(0xffffffffu, mx0, 2));
            mx1 = fmaxf(mx1, __shfl_xor_sync(0xffffffffu, mx1, 1));
            mx1 = fmaxf(mx1, __shfl_xor_sync(0xffffffffu, mx1, 2));

            float s0 = 0.f, s1 = 0.f;
            #pragma unroll
            for (int j = 0; j < 16; j++) {
                v0[j] = __expf(v0[j] - mx0); s0 += v0[j];
                v1[j] = __expf(v1[j] - mx1); s1 += v1[j];
            }
            s0 += __shfl_xor_sync(0xffffffffu, s0, 1);
            s0 += __shfl_xor_sync(0xffffffffu, s0, 2);
            s1 += __shfl_xor_sync(0xffffffffu, s1, 1);
            s1 += __shfl_xor_sync(0xffffffffu, s1, 2);
            const float inv0 = 1.0f / s0, inv1 = 1.0f / s1;
            #pragma unroll
            for (int j = 0; j < 16; j++) { v0[j] *= inv0; v1[j] *= inv1; }
        }

        // ---- PV ----
        float oacc[4][4] = {};
        #pragma unroll
        for (int kt = 0; kt < 4; kt++) {
            uint32_t afr[4];
            afr[0] = h2bits(v0[4 * kt],     v0[4 * kt + 1]);
            afr[1] = h2bits(v1[4 * kt],     v1[4 * kt + 1]);
            afr[2] = h2bits(v0[4 * kt + 2], v0[4 * kt + 3]);
            afr[3] = h2bits(v1[4 * kt + 2], v1[4 * kt + 3]);
            #pragma unroll
            for (int p = 0; p < 2; p++) {
                uint32_t bfr[4];
                ldsm_x4t(bfr, aV + kt * 16 * 80 + p * 32);
                mma16(oacc[p * 2],     afr, &bfr[0]);
                mma16(oacc[p * 2 + 1], afr, &bfr[2]);
            }
        }

        // ---- output ----
        {
            const int b = w + 64 * (grp * 8 + i);
            float* ob = out + (size_t)b * (NTOK * DIM) + h * HEADDIM;
            #pragma unroll
            for (int nt = 0; nt < 4; nt++) {
                const int c0 = nt * 8 + tg * 2;
                *(float2*)(ob + (size_t)r0 * DIM + c0)       = make_float2(oacc[nt][0], oacc[nt][1]);
                *(float2*)(ob + (size_t)(r0 + 8) * DIM + c0) = make_float2(oacc[nt][2], oacc[nt][3]);
            }
        }
    }
}

// ---------------------------------------------------------------------------
extern "C" void kernel_launch(void* const* d_in, const int* in_sizes, int n_in,
                              void* d_out, int out_size)
{
    const float* hs   = (const float*)d_in[0];
    const float* mask = (const float*)d_in[1];
    const float* wq   = (const float*)d_in[2];
    const float* bq   = (const float*)d_in[3];
    const float* wk   = (const float*)d_in[4];
    const float* bk   = (const float*)d_in[5];
    const float* wv   = (const float*)d_in[6];
    const float* bv   = (const float*)d_in[7];
    const float* bt   = (const float*)d_in[8];
    const int*   ri   = (const int*)d_in[9];
    float* out = (float*)d_out;

    static bool attr_set = false;
    if (!attr_set) {
        cudaFuncSetAttribute(qkv_gemm_tc,
                             cudaFuncAttributeMaxDynamicSharedMemorySize, GEMM_SMEM);
        attr_set = true;
    }

    prep_all<<<24672, 256>>>(hs, wq, wk, wv, mask, bt, ri);

    qkv_gemm_tc<<<(BATCH * NTOK) / 128, 256, GEMM_SMEM>>>(bq, bk, bv);

    dim3 attn_grid(MASK_NW, HEADS, 4);
    attn_tc<<<attn_grid, 128>>>(out);
}

// round 16
// speedup vs baseline: 1.1826x; 1.0509x over previous
#include <cuda_runtime.h>
#include <cuda_fp16.h>
#include <cstdint>

#define BATCH   2048
#define NTOK    64
#define DIM     256
#define HEADS   8
#define HEADDIM 32
#define MASK_NW 64

// fp16 staging: X, W (q|k|v); Q/K/V scratch in HEAD-MAJOR layout
// [h][b][64][32]; CMB fp32
__device__ __half g_Xh[(size_t)BATCH * NTOK * DIM];
__device__ __half g_Wh[3 * DIM * DIM];
__device__ __half g_Q[(size_t)BATCH * NTOK * DIM];
__device__ __half g_K[(size_t)BATCH * NTOK * DIM];
__device__ __half g_V[(size_t)BATCH * NTOK * DIM];
__device__ float  g_CMB[(size_t)MASK_NW * HEADS * NTOK * NTOK];

__device__ __forceinline__ uint32_t h2bits(float a, float b) {
    __half2 h = __floats2half2_rn(a, b);
    return *(uint32_t*)&h;
}
__device__ __forceinline__ uint32_t smem_u32(const void* p) {
    return (uint32_t)__cvta_generic_to_shared(p);
}
__device__ __forceinline__ void ldsm_x4(uint32_t* r, uint32_t a) {
    asm volatile("ldmatrix.sync.aligned.m8n8.x4.shared.b16 {%0,%1,%2,%3}, [%4];"
        : "=r"(r[0]), "=r"(r[1]), "=r"(r[2]), "=r"(r[3]) : "r"(a));
}
__device__ __forceinline__ void ldsm_x4t(uint32_t* r, uint32_t a) {
    asm volatile("ldmatrix.sync.aligned.m8n8.x4.trans.shared.b16 {%0,%1,%2,%3}, [%4];"
        : "=r"(r[0]), "=r"(r[1]), "=r"(r[2]), "=r"(r[3]) : "r"(a));
}
__device__ __forceinline__ void mma16(float* d, const uint32_t* a, const uint32_t* b) {
    asm("mma.sync.aligned.m16n8k16.row.col.f32.f16.f16.f32 "
        "{%0,%1,%2,%3}, {%4,%5,%6,%7}, {%8,%9}, {%0,%1,%2,%3};"
        : "+f"(d[0]), "+f"(d[1]), "+f"(d[2]), "+f"(d[3])
        : "r"(a[0]), "r"(a[1]), "r"(a[2]), "r"(a[3]), "r"(b[0]), "r"(b[1]));
}
__device__ __forceinline__ void cp16(uint32_t dst, const void* src) {
    asm volatile("cp.async.cg.shared.global [%0], [%1], 16;" :: "r"(dst), "l"(src));
}
__device__ __forceinline__ void cp_commit() {
    asm volatile("cp.async.commit_group;");
}
template <int N>
__device__ __forceinline__ void cp_wait() {
    asm volatile("cp.async.wait_group %0;" :: "n"(N));
}

// ---------------------------------------------------------------------------
// Kernel 0: one-shot prep. Blocks [0,16384): X fp32->fp16; [16384,16480): W;
// [16480,24672): combined mask + rel-bias.
// ---------------------------------------------------------------------------
__global__ void prep_all(const float* __restrict__ X,
                         const float* __restrict__ Wq,
                         const float* __restrict__ Wk,
                         const float* __restrict__ Wv,
                         const float* __restrict__ mask,
                         const float* __restrict__ bt,
                         const int*   __restrict__ ri)
{
    const int bid = blockIdx.x;
    if (bid < 16384) {
        const size_t i8 = ((size_t)bid * 256 + threadIdx.x) * 8;
        const float4 a = *(const float4*)(X + i8);
        const float4 b = *(const float4*)(X + i8 + 4);
        uint32_t r[4] = { h2bits(a.x, a.y), h2bits(a.z, a.w),
                          h2bits(b.x, b.y), h2bits(b.z, b.w) };
        *(uint4*)(g_Xh + i8) = *(uint4*)r;
    } else if (bid < 16384 + 96) {
        const int i8 = ((bid - 16384) * 256 + threadIdx.x) * 8;
        const int t3 = i8 >> 16;
        const int off = i8 & 65535;
        const float* src = (t3 == 0) ? Wq : (t3 == 1) ? Wk : Wv;
        const float4 a = *(const float4*)(src + off);
        const float4 b = *(const float4*)(src + off + 4);
        uint32_t r[4] = { h2bits(a.x, a.y), h2bits(a.z, a.w),
                          h2bits(b.x, b.y), h2bits(b.z, b.w) };
        *(uint4*)(g_Wh + i8) = *(uint4*)r;
    } else {
        const int idx = (bid - 16480) * 256 + threadIdx.x;
        const int p = idx & 4095;
        const int h = (idx >> 12) & 7;
        const int w = idx >> 15;
        g_CMB[idx] = mask[w * 4096 + p] + bt[ri[p] * 8 + h];
    }
}

// ---------------------------------------------------------------------------
// Kernel 1: X-resident QKV GEMM (R11/R13 verified). One CTA per 128-row
//   m-block; 4-stage cp.async weight pipeline across 6 slabs; 8 warps;
//   2 CTA/SM. Epilogue stores to HEAD-MAJOR scratch.
// ---------------------------------------------------------------------------
#define GEMM_SMEM (128 * 256 * 2 + 4 * 128 * 40 * 2)   // 106496 B

__global__ __launch_bounds__(256, 2) void qkv_gemm_tc(
    const float* __restrict__ Bq, const float* __restrict__ Bk,
    const float* __restrict__ Bv)
{
    extern __shared__ __half sm[];
    __half* Xs  = sm;                 // 128 x 256, swizzled, 512 B rows
    __half* Bsm = sm + 128 * 256;     // 4 stages x 128 x 40

    const int tid  = threadIdx.x;
    const int m0   = blockIdx.x * 128;
    const int lane = tid & 31;
    const int warp = tid >> 5;
    const int g  = lane >> 2;
    const int tg = lane & 3;
    const int wm = (warp >> 1) * 32;
    const int wn = (warp & 1) * 64;

    const uint32_t XsB = smem_u32(Xs);
    const uint32_t BsB = smem_u32(Bsm);
    constexpr uint32_t BSTG = 128 * 40 * 2;

    // ---- one-time X tile load (swizzled) -> commit group 0 ----
    {
        const int ar = tid >> 1;
        const int ah = tid & 1;
        const __half* xsrc = g_Xh + (size_t)(m0 + ar) * DIM + ah * 128;
        const uint32_t rbase = XsB + ar * 512;
        const int sw = (ar & 7) << 4;
        #pragma unroll
        for (int i = 0; i < 16; i++) {
            const int col = ah * 256 + i * 16;
            cp16(rbase + (col ^ sw), xsrc + i * 8);
        }
        cp_commit();
    }

    // ---- B stage load ----
    const int br = tid >> 1;
    const int bh = (tid & 1) * 16;
    const uint32_t bdst = BsB + (br * 40 + bh) * 2;

    auto bsrc = [&](int it) -> const __half* {
        const int nsel = it >> 3, kt = it & 7;
        const int t3 = nsel >> 1, nl0 = (nsel & 1) << 7;
        return g_Wh + t3 * 65536 + (size_t)(nl0 + br) * 256 + kt * 32 + bh;
    };

    #pragma unroll
    for (int p = 0; p < 3; p++) {
        const __half* sp = bsrc(p);
        cp16(bdst + p * BSTG,      sp);
        cp16(bdst + p * BSTG + 16, sp + 8);
        cp_commit();
    }

    // ---- ldmatrix lane addresses ----
    const int ra = (lane & 7) + ((lane >> 3) & 1) * 8;
    const int cab = (lane >> 4) * 16;
    uint32_t aArow[2]; int aAsw[2];
    #pragma unroll
    for (int mt = 0; mt < 2; mt++) {
        const int rr = wm + mt * 16 + ra;
        aArow[mt] = XsB + rr * 512;
        aAsw[mt]  = (rr & 7) << 4;
    }
    const int nb = (lane & 7) + (lane >> 4) * 8;
    const int kb = ((lane >> 3) & 1) * 8;
    const uint32_t aB = BsB + ((wn + nb) * 40 + kb) * 2;

    float acc[2][8][4] = {};

    for (int nsel = 0; nsel < 6; nsel++) {
        #pragma unroll
        for (int kt = 0; kt < 8; kt++) {
            const int it = nsel * 8 + kt;
            cp_wait<2>();
            __syncthreads();

            if (it + 3 < 48) {
                const uint32_t sn = ((it + 3) & 3) * BSTG;
                const __half* s3 = bsrc(it + 3);
                cp16(bdst + sn,      s3);
                cp16(bdst + sn + 16, s3 + 8);
            }
            cp_commit();

            const uint32_t s = (it & 3) * BSTG;
            uint32_t afr[2][2][4];
            uint32_t bfr[2][4][4];
            #pragma unroll
            for (int kcb = 0; kcb < 2; kcb++) {
                const int akb = (kt * 32 + kcb * 16) * 2 + cab;
                ldsm_x4(afr[kcb][0], aArow[0] + (akb ^ aAsw[0]));
                ldsm_x4(afr[kcb][1], aArow[1] + (akb ^ aAsw[1]));
                #pragma unroll
                for (int j = 0; j < 4; j++)
                    ldsm_x4(bfr[kcb][j], aB + s + j * 1280 + kcb * 32);
            }
            #pragma unroll
            for (int kcb = 0; kcb < 2; kcb++)
                #pragma unroll
                for (int mt = 0; mt < 2; mt++)
                    #pragma unroll
                    for (int nt = 0; nt < 8; nt++)
                        mma16(acc[mt][nt], afr[kcb][mt],
                              &bfr[kcb][nt >> 1][(nt & 1) * 2]);
        }

        // ---- slab epilogue: bias add + HEAD-MAJOR store, reset acc ----
        {
            const int t3  = nsel >> 1;
            const int nl0 = (nsel & 1) << 7;
            const float* bias = (t3 == 0) ? Bq : (t3 == 1) ? Bk : Bv;
            __half* outp      = (t3 == 0) ? g_Q : (t3 == 1) ? g_K : g_V;
            #pragma unroll
            for (int nt = 0; nt < 8; nt++) {
                const int c = nl0 + wn + nt * 8 + tg * 2;
                const float b0 = bias[c], b1 = bias[c + 1];
                const size_t hbase = (size_t)(c >> 5) * (BATCH * NTOK) * HEADDIM
                                   + (c & 31);
                #pragma unroll
                for (int mt = 0; mt < 2; mt++) {
                    const int r = m0 + wm + mt * 16 + g;
                    *(uint32_t*)(outp + hbase + (size_t)r * HEADDIM) =
                        h2bits(acc[mt][nt][0] + b0, acc[mt][nt][1] + b1);
                    *(uint32_t*)(outp + hbase + (size_t)(r + 8) * HEADDIM) =
                        h2bits(acc[mt][nt][2] + b0, acc[mt][nt][3] + b1);
                    acc[mt][nt][0] = 0.f; acc[mt][nt][1] = 0.f;
                    acc[mt][nt][2] = 0.f; acc[mt][nt][3] = 0.f;
                }
            }
        }
    }
}

// ---------------------------------------------------------------------------
// Kernel 2: window-batched fp16 attention (R13 verified), now reading dense
// head-major Q/K/V tiles (4 KB contiguous per tensor per window).
// ---------------------------------------------------------------------------
__global__ __launch_bounds__(128) void attn_tc(float* __restrict__ out)
{
    __shared__ float  cmbs[4096];
    __shared__ __half qkv[2][3][64 * 40];

    const int w   = blockIdx.x;
    const int h   = blockIdx.y;
    const int grp = blockIdx.z;
    const int tid  = threadIdx.x;
    const int lane = tid & 31;
    const int warp = tid >> 5;
    const int g  = lane >> 2;
    const int tg = lane & 3;

    {
        const float* cmb_g = g_CMB + (((size_t)w * HEADS + h) << 12);
        #pragma unroll
        for (int i = 0; i < 8; i++)
            ((float4*)cmbs)[tid + i * 128] = ((const float4*)cmb_g)[tid + i * 128];
    }

    const int r  = tid >> 1;
    const int ch = (tid & 1) * 16;
    const uint32_t qkvB = smem_u32(&qkv[0][0][0]);
    constexpr uint32_t TBUF = 3 * 64 * 40 * 2;
    constexpr uint32_t TTEN = 64 * 40 * 2;
    const uint32_t ldst = (r * 40 + ch) * 2;
    const size_t hoff = (size_t)h * (BATCH * NTOK) * HEADDIM;

    auto qkv_load = [&](int i, int buf) {
        const int b = w + 64 * (grp * 8 + i);
        const size_t go = hoff + ((size_t)b * NTOK + r) * HEADDIM + ch;
        const uint32_t d = qkvB + buf * TBUF + ldst;
        cp16(d,                 g_Q + go);
        cp16(d + 16,            g_Q + go + 8);
        cp16(d + TTEN,          g_K + go);
        cp16(d + TTEN + 16,     g_K + go + 8);
        cp16(d + 2 * TTEN,      g_V + go);
        cp16(d + 2 * TTEN + 16, g_V + go + 8);
    };

    qkv_load(0, 0);
    cp_commit();

    const int ra = (lane & 7) + ((lane >> 3) & 1) * 8;
    const int ca = (lane >> 4) * 8;
    const uint32_t oQ = ((warp * 16 + ra) * 40 + ca) * 2;
    const int nb = (lane & 7) + (lane >> 4) * 8;
    const int kb = ((lane >> 3) & 1) * 8;
    const uint32_t oK = TTEN + (nb * 40 + kb) * 2;
    const uint32_t oV = 2 * TTEN + (ra * 40 + ca) * 2;

    const float scale = 0.17677669529663687f;
    const int r0 = warp * 16 + g;

    for (int i = 0; i < 8; i++) {
        cp_wait<0>();
        __syncthreads();

        if (i < 7) qkv_load(i + 1, (i + 1) & 1);
        cp_commit();

        const uint32_t base = qkvB + (i & 1) * TBUF;
        const uint32_t aQ = base + oQ;
        const uint32_t aK = base + oK;
        const uint32_t aV = base + oV;

        float sacc[8][4] = {};
        #pragma unroll
        for (int kc = 0; kc < HEADDIM; kc += 16) {
            uint32_t afr[4];
            ldsm_x4(afr, aQ + kc * 2);
            #pragma unroll
            for (int j = 0; j < 4; j++) {
                uint32_t bfr[4];
                ldsm_x4(bfr, aK + j * 16 * 80 + kc * 2);
                mma16(sacc[j * 2],     afr, &bfr[0]);
                mma16(sacc[j * 2 + 1], afr, &bfr[2]);
            }
        }

        float v0[16], v1[16];
        #pragma unroll
        for (int nt = 0; nt < 8; nt++) {
            const int c0 = nt * 8 + tg * 2;
            const float2 m0v = *(const float2*)&cmbs[r0 * 64 + c0];
            const float2 m1v = *(const float2*)&cmbs[(r0 + 8) * 64 + c0];
            v0[nt * 2]     = sacc[nt][0] * scale + m0v.x;
            v0[nt * 2 + 1] = sacc[nt][1] * scale + m0v.y;
            v1[nt * 2]     = sacc[nt][2] * scale + m1v.x;
            v1[nt * 2 + 1] = sacc[nt][3] * scale + m1v.y;
        }

        {
            float mx0 = v0[0], mx1 = v1[0];
            #pragma unroll
            for (int j = 1; j < 16; j++) { mx0 = fmaxf(mx0, v0[j]); mx1 = fmaxf(mx1, v1[j]); }
            mx0 = fmaxf(mx0, __shfl_xor_sync(0xffffffffu, mx0, 1));
            mx0 = fmaxf(mx0, __shfl_xor_sync(0xffffffffu, mx0, 2));
            mx1 = fmaxf(mx1, __shfl_xor_sync(0xffffffffu, mx1, 1));
            mx1 = fmaxf(mx1, __shfl_xor_sync(0xffffffffu, mx1, 2));

            float s0 = 0.f, s1 = 0.f;
            #pragma unroll
            for (int j = 0; j < 16; j++) {
                v0[j] = __expf(v0[j] - mx0); s0 += v0[j];
                v1[j] = __expf(v1[j] - mx1); s1 += v1[j];
            }
            s0 += __shfl_xor_sync(0xffffffffu, s0, 1);
            s0 += __shfl_xor_sync(0xffffffffu, s0, 2);
            s1 += __shfl_xor_sync(0xffffffffu, s1, 1);
            s1 += __shfl_xor_sync(0xffffffffu, s1, 2);
            const float inv0 = 1.0f / s0, inv1 = 1.0f / s1;
            #pragma unroll
            for (int j = 0; j < 16; j++) { v0[j] *= inv0; v1[j] *= inv1; }
        }

        float oacc[4][4] = {};
        #pragma unroll
        for (int kt = 0; kt < 4; kt++) {
            uint32_t afr[4];
            afr[0] = h2bits(v0[4 * kt],     v0[4 * kt + 1]);
            afr[1] = h2bits(v1[4 * kt],     v1[4 * kt + 1]);
            afr[2] = h2bits(v0[4 * kt + 2], v0[4 * kt + 3]);
            afr[3] = h2bits(v1[4 * kt + 2], v1[4 * kt + 3]);
            #pragma unroll
            for (int p = 0; p < 2; p++) {
                uint32_t bfr[4];
                ldsm_x4t(bfr, aV + kt * 16 * 80 + p * 32);
                mma16(oacc[p * 2],     afr, &bfr[0]);
                mma16(oacc[p * 2 + 1], afr, &bfr[2]);
            }
        }

        {
            const int b = w + 64 * (grp * 8 + i);
            float* ob = out + (size_t)b * (NTOK * DIM) + h * HEADDIM;
            #pragma unroll
            for (int nt = 0; nt < 4; nt++) {
                const int c0 = nt * 8 + tg * 2;
                *(float2*)(ob + (size_t)r0 * DIM + c0)       = make_float2(oacc[nt][0], oacc[nt][1]);
                *(float2*)(ob + (size_t)(r0 + 8) * DIM + c0) = make_float2(oacc[nt][2], oacc[nt][3]);
            }
        }
    }
}

// ---------------------------------------------------------------------------
extern "C" void kernel_launch(void* const* d_in, const int* in_sizes, int n_in,
                              void* d_out, int out_size)
{
    const float* hs   = (const float*)d_in[0];
    const float* mask = (const float*)d_in[1];
    const float* wq   = (const float*)d_in[2];
    const float* bq   = (const float*)d_in[3];
    const float* wk   = (const float*)d_in[4];
    const float* bk   = (const float*)d_in[5];
    const float* wv   = (const float*)d_in[6];
    const float* bv   = (const float*)d_in[7];
    const float* bt   = (const float*)d_in[8];
    const int*   ri   = (const int*)d_in[9];
    float* out = (float*)d_out;

    static bool attr_set = false;
    if (!attr_set) {
        cudaFuncSetAttribute(qkv_gemm_tc,
                             cudaFuncAttributeMaxDynamicSharedMemorySize, GEMM_SMEM);
        attr_set = true;
    }

    prep_all<<<24672, 256>>>(hs, wq, wk, wv, mask, bt, ri);

    qkv_gemm_tc<<<(BATCH * NTOK) / 128, 256, GEMM_SMEM>>>(bq, bk, bv);

    dim3 attn_grid(MASK_NW, HEADS, 4);
    attn_tc<<<attn_grid, 128>>>(out);
}